// round 11
// baseline (speedup 1.0000x reference)
#include <cuda_runtime.h>
#include <math.h>

#define BB 16
#define NN 100
#define CC 100

__device__ float  g_cost[BB * NN * NN];
__device__ int    g_col[BB * NN];
__device__ double g_partial[BB];

// ---------------------------------------------------------------------------
// Kernel 1: cost matrix, fp32 in the reference's exact op order.
// ---------------------------------------------------------------------------
__global__ void cost_kernel(const float* __restrict__ bbox_pred,
                            const float* __restrict__ labels_pred,
                            const float* __restrict__ bbox_gt,
                            const int*   __restrict__ labels_gt)
{
    int b = blockIdx.x;
    __shared__ float4 s_pr[NN];
    __shared__ float4 s_gt[NN];
    __shared__ int    s_lab[NN];
    for (int i = threadIdx.x; i < NN; i += blockDim.x) {
        s_pr[i]  = ((const float4*)bbox_pred)[b * NN + i];
        s_gt[i]  = ((const float4*)bbox_gt)[b * NN + i];
        s_lab[i] = labels_gt[b * NN + i];
    }
    __syncthreads();

    for (int idx = threadIdx.x; idx < NN * NN; idx += blockDim.x) {
        int q = idx / NN;
        int g = idx % NN;
        float4 p = s_pr[q];
        float4 t = s_gt[g];

        float pulx = p.x - 0.5f * p.z, puly = p.y - 0.5f * p.w;
        float pdrx = p.x + 0.5f * p.z, pdry = p.y + 0.5f * p.w;
        float gulx = t.x - 0.5f * t.z, guly = t.y - 0.5f * t.w;
        float gdrx = t.x + 0.5f * t.z, gdry = t.y + 0.5f * t.w;

        float iw = fmaxf(fminf(pdrx, gdrx) - fmaxf(pulx, gulx) + 1.0f, 0.0f);
        float ih = fmaxf(fminf(pdry, gdry) - fmaxf(puly, guly) + 1.0f, 0.0f);
        float inter = iw * ih;

        float pw = fmaxf(pdrx - pulx + 1.0f, 0.0f);
        float ph = fmaxf(pdry - puly + 1.0f, 0.0f);
        float gw = fmaxf(gdrx - gulx + 1.0f, 0.0f);
        float gh = fmaxf(gdry - guly + 1.0f, 0.0f);
        float uni = pw * ph + gw * gh - inter;
        float iou = inter / fmaxf(uni, 1e-9f);

        float bw = fmaxf(fmaxf(pdrx, gdrx) - fminf(pulx, gulx) + 1.0f, 0.0f);
        float bh = fmaxf(fmaxf(pdry, gdry) - fminf(puly, guly) + 1.0f, 0.0f);
        float bound = bw * bh;
        float bgr = (bound - uni) / fmaxf(bound, 1e-9f);

        float l1 = fabsf(p.x - t.x) + fabsf(p.y - t.y) +
                   fabsf(p.z - t.z) + fabsf(p.w - t.w);

        float prob = labels_pred[(b * NN + q) * CC + s_lab[g]];

        g_cost[(b * NN + q) * NN + g] = l1 - (iou - bgr) - prob;
    }
}

// ---------------------------------------------------------------------------
// fp32 sortable-key helper: 32-bit key whose ordering == fp32 ordering.
// ---------------------------------------------------------------------------
__device__ __forceinline__ unsigned f2key(float f)
{
    int b = __float_as_int(f);
    return (unsigned)(b ^ ((b >> 31) | 0x80000000));
}

// ---------------------------------------------------------------------------
// Kernel 2: JV Hungarian, one warp per batch, fp32 Dijkstra.
// vs R10: single-REDUX argmin. Per-slot packed keys pk = (key & ~0x7F) | j
// (j<=100 fits 7 bits) are maintained off the critical path; the lane
// tournament is two pure u32 mins and ONE __reduce_min_sync gives j1
// directly. delta = the chosen column's exact fp32 minv, fetched via one
// shfl from the owner lane (parallel to the cinfo/crow loads). Key
// truncation (~8e-6 rel) only reorders near-tied expansions; assignment
// gaps ~1e-4 keep the final assignment identical.
// ---------------------------------------------------------------------------
__global__ void __launch_bounds__(32, 1) hungarian_kernel()
{
    const int b    = blockIdx.x;
    const int lane = threadIdx.x;
    const unsigned FULL   = 0xffffffffu;
    const unsigned KMAX32 = 0xffffffffu;

    __shared__ float  sc[NN * NN];      // 40 KB cost
    __shared__ float  su[NN + 1];       // row duals
    __shared__ float2 cinfo[NN + 1];    // per column: .x = u[sp[j]], .y = bits(sp[j])
    __shared__ int    sp[NN + 1];       // column -> row
    __shared__ int    sway[NN + 1];     // augmenting-path predecessors
    __shared__ int    sargmin[NN + 1];  // column-reduction argmin rows
    __shared__ unsigned char srowass[NN + 1];  // greedy row-assigned flags

    const float* gc = g_cost + b * NN * NN;
    for (int t = lane; t < NN * NN; t += 32) sc[t] = gc[t];
    for (int j = lane; j <= NN; j += 32) {
        su[j] = 0.0f; sp[j] = 0; sway[j] = 0; srowass[j] = 0;
    }
    __syncwarp();

    const int jbase = 4 * lane + 1;
    const int coff  = (lane < 25) ? 4 * lane : 96;   // clamped float4 offset
    const unsigned pad = (lane < 25) ? 0u : KMAX32;  // key poison

    // ---- column reduction: v[j] = min_i c[i][j], first-argmin row ----
    float vminf[4] = {INFINITY, INFINITY, INFINITY, INFINITY};
    int   rmin[4]  = {1, 1, 1, 1};
    for (int r = 0; r < NN; r++) {
        float4 cf = *(const float4*)(sc + r * NN + coff);
        float cv[4] = {cf.x, cf.y, cf.z, cf.w};
        #pragma unroll
        for (int s = 0; s < 4; s++)
            if (cv[s] < vminf[s]) { vminf[s] = cv[s]; rmin[s] = r + 1; }
    }
    if (lane < 25) {
        #pragma unroll
        for (int s = 0; s < 4; s++) sargmin[jbase + s] = rmin[s];
    }
    __syncwarp();

    // ---- greedy assignment (serial, lane 0) ----
    if (lane == 0) {
        for (int j = 1; j <= NN; j++) {
            int r = sargmin[j];
            if (!srowass[r]) { srowass[r] = 1; sp[j] = r; }
        }
    }
    __syncwarp();
    if (lane < 25) {
        #pragma unroll
        for (int s = 0; s < 4; s++) {
            int jj = jbase + s;
            cinfo[jj] = make_float2(0.0f, __int_as_float(sp[jj]));
        }
    }
    __syncwarp();

    float v[4];
    #pragma unroll
    for (int s = 0; s < 4; s++) v[s] = vminf[s];

    // ---- augmenting Dijkstra (fp32) for unassigned rows only ----
    for (int i = 1; i <= NN; i++) {
        if (srowass[i]) continue;      // uniform branch (shared broadcast)

        float    minv[4];
        unsigned mkey[4];
        unsigned pk[4];                // packed (key & ~0x7F) | column-index
        int      pj[4] = {0, 0, 0, 0};
        float    t4[4];
        #pragma unroll
        for (int s = 0; s < 4; s++) {
            minv[s] = INFINITY; mkey[s] = KMAX32; pk[s] = KMAX32;
            t4[s] = v[s];              // u[i] = 0 at insertion
        }
        unsigned usedm = 0;

        int   j0  = 0;
        int   i0  = i;
        float acc = 0.0f;              // running sum of deltas == u[i]

        while (true) {
            // mark used[j0] (only owner lane matches; never a padding lane)
            #pragma unroll
            for (int s = 0; s < 4; s++)
                if (j0 == jbase + s) {
                    usedm |= 1u << s; mkey[s] = KMAX32; pk[s] = KMAX32; pj[s] = i0;
                }

            // scan: straight-line, predicated, all-fp32
            const float* crow = sc + (i0 - 1) * NN;
            float4 cf = *(const float4*)(crow + coff);
            float c[4] = {cf.x, cf.y, cf.z, cf.w};
            #pragma unroll
            for (int s = 0; s < 4; s++) {
                if (!((usedm >> s) & 1u)) {
                    float cur = c[s] - t4[s];           // t4 = u[i0] + v[s]
                    unsigned ck = f2key(cur) | pad;
                    if (ck < mkey[s]) {
                        mkey[s] = ck; minv[s] = cur; sway[jbase + s] = j0;
                        pk[s] = (ck & 0xFFFFFF80u) | (unsigned)(jbase + s);
                    }
                }
            }
            // pure-min tournament (index embedded in low 7 bits)
            unsigned bkey = min(min(pk[0], pk[1]), min(pk[2], pk[3]));

            // ONE warp REDUX: winner column in low 7 bits
            unsigned m  = __reduce_min_sync(FULL, bkey);
            int      j1 = (int)(m & 0x7Fu);

            // exact delta: shfl winner's fp32 minv from its owner lane
            int sidx  = (j1 - 1) & 3;
            int owner = (j1 - 1) >> 2;
            float m01 = (sidx & 1) ? minv[1] : minv[0];
            float m23 = (sidx & 1) ? minv[3] : minv[2];
            float selv = (sidx & 2) ? m23 : m01;
            float delta = __shfl_sync(FULL, selv, owner);

            // dual updates (su addresses lane-owned; never padding lanes)
            #pragma unroll
            for (int s = 0; s < 4; s++) {
                if ((usedm >> s) & 1u) {
                    su[pj[s]] += delta;
                    v[s] -= delta;
                } else {
                    minv[s] -= delta;
                    unsigned nk = f2key(minv[s]) | pad;
                    mkey[s] = nk;
                    pk[s]   = (nk & 0xFFFFFF80u) | (unsigned)(jbase + s);
                }
            }
            acc += delta;

            // single 64-bit LDS: {u[sp[j1]], sp[j1]} — frozen during the run
            float2 ci = cinfo[j1];
            int i0n = __float_as_int(ci.y);
            if (i0n == 0) { j0 = j1; break; }
            j0 = j1;
            i0 = i0n;
            // hoisted t for next iteration (off the LDS critical path)
            #pragma unroll
            for (int s = 0; s < 4; s++) t4[s] = ci.x + v[s];
        }

        // augment (serial, lane 0); write back u[i] once
        __syncwarp();
        if (lane == 0) {
            su[i]  = acc;
            sp[0]  = i;
            int jj = j0;
            while (jj) { int jn = sway[jj]; sp[jj] = sp[jn]; jj = jn; }
        }
        __syncwarp();

        // refresh cached {u,row} for used columns AND the break column j0
        #pragma unroll
        for (int s = 0; s < 4; s++) {
            int jj = jbase + s;
            if (((usedm >> s) & 1u) || (jj == j0)) {
                int r = sp[jj];
                cinfo[jj] = make_float2(su[r], __int_as_float(r));
            }
        }
        __syncwarp();
    }

    for (int j = lane + 1; j <= NN; j += 32)
        g_col[b * NN + (sp[j] - 1)] = j - 1;
}

// ---------------------------------------------------------------------------
// Kernel 3: per-batch losses.
// ---------------------------------------------------------------------------
__global__ void loss_kernel(const float* __restrict__ bbox_pred,
                            const float* __restrict__ labels_pred,
                            const float* __restrict__ bbox_gt,
                            const int*   __restrict__ labels_gt)
{
    int b   = blockIdx.x;
    int tid = threadIdx.x;  // 128

    double nll_sum = 0.0, reg_sum = 0.0, giou_sum = 0.0;

    for (int q = tid; q < NN; q += blockDim.x) {
        int cg  = g_col[b * NN + q];
        int lab = labels_gt[b * NN + cg];

        const float* pr = labels_pred + (size_t)(b * NN + q) * CC;
        double se = 0.0;
        float  plab = 0.0f;
        for (int c = 0; c < CC; c++) {
            float pc = fminf(fmaxf(pr[c], 1e-7f), 1.0f - 1e-7f);
            se += (double)pc;
            if (c == lab) plab = pc;
        }
        nll_sum += log(se) - (double)logf(plab);

        float4 p = ((const float4*)bbox_pred)[b * NN + q];
        float4 t = ((const float4*)bbox_gt)[b * NN + cg];
        reg_sum += (double)(fabsf(p.x - t.x) + fabsf(p.y - t.y) +
                            fabsf(p.z - t.z) + fabsf(p.w - t.w));

        float4 g = ((const float4*)bbox_gt)[b * NN + q];
        float pulx = p.x - 0.5f * p.z, puly = p.y - 0.5f * p.w;
        float pdrx = p.x + 0.5f * p.z, pdry = p.y + 0.5f * p.w;
        float gulx = g.x - 0.5f * g.z, guly = g.y - 0.5f * g.w;
        float gdrx = g.x + 0.5f * g.z, gdry = g.y + 0.5f * g.w;
        float iw = fmaxf(fminf(pdrx, gdrx) - fmaxf(pulx, gulx) + 1.0f, 0.0f);
        float ih = fmaxf(fminf(pdry, gdry) - fmaxf(puly, guly) + 1.0f, 0.0f);
        float inter = iw * ih;
        float pw = fmaxf(pdrx - pulx + 1.0f, 0.0f);
        float ph = fmaxf(pdry - puly + 1.0f, 0.0f);
        float gw = fmaxf(gdrx - gulx + 1.0f, 0.0f);
        float gh = fmaxf(gdry - guly + 1.0f, 0.0f);
        float uni = pw * ph + gw * gh - inter;
        float iou = inter / fmaxf(uni, 1e-9f);
        float bw = fmaxf(fmaxf(pdrx, gdrx) - fminf(pulx, gulx) + 1.0f, 0.0f);
        float bh = fmaxf(fmaxf(pdry, gdry) - fminf(puly, guly) + 1.0f, 0.0f);
        float bound = bw * bh;
        float bgr = (bound - uni) / fmaxf(bound, 1e-9f);
        giou_sum += (double)(iou - bgr);
    }

    __shared__ double s0[128], s1[128], s2[128];
    s0[tid] = nll_sum; s1[tid] = reg_sum; s2[tid] = giou_sum;
    __syncthreads();
    for (int s = 64; s; s >>= 1) {
        if (tid < s) { s0[tid] += s0[tid + s]; s1[tid] += s1[tid + s]; s2[tid] += s2[tid + s]; }
        __syncthreads();
    }
    if (tid == 0) {
        double per = s0[0] / NN + 5.0 * (s1[0] / (NN * 4.0)) + 2.0 * (s2[0] / NN);
        g_partial[b] = per;
    }
}

__global__ void final_kernel(float* __restrict__ out)
{
    double s = 0.0;
    for (int b = 0; b < BB; b++) s += g_partial[b];
    out[0] = (float)s;
}

// ---------------------------------------------------------------------------
extern "C" void kernel_launch(void* const* d_in, const int* in_sizes, int n_in,
                              void* d_out, int out_size)
{
    const float* bbox_pred   = (const float*)d_in[0];
    const float* labels_pred = (const float*)d_in[1];
    const float* bbox_gt     = (const float*)d_in[2];
    const int*   labels_gt   = (const int*)d_in[3];

    cost_kernel<<<BB, 256>>>(bbox_pred, labels_pred, bbox_gt, labels_gt);
    hungarian_kernel<<<BB, 32>>>();
    loss_kernel<<<BB, 128>>>(bbox_pred, labels_pred, bbox_gt, labels_gt);
    final_kernel<<<1, 1>>>((float*)d_out);
}

// round 14
// speedup vs baseline: 1.3095x; 1.3095x over previous
#include <cuda_runtime.h>
#include <math.h>

#define BB 16
#define NN 100
#define CC 100
#define QCAP 416   // >= max initial free rows (100) + max appends (300 steps)

__device__ float  g_cost[BB * NN * NN];
__device__ int    g_col[BB * NN];
__device__ double g_partial[BB];

// ---------------------------------------------------------------------------
// Kernel 1: cost matrix, fp32 in the reference's exact op order.
// ---------------------------------------------------------------------------
__global__ void cost_kernel(const float* __restrict__ bbox_pred,
                            const float* __restrict__ labels_pred,
                            const float* __restrict__ bbox_gt,
                            const int*   __restrict__ labels_gt)
{
    int b = blockIdx.x;
    __shared__ float4 s_pr[NN];
    __shared__ float4 s_gt[NN];
    __shared__ int    s_lab[NN];
    for (int i = threadIdx.x; i < NN; i += blockDim.x) {
        s_pr[i]  = ((const float4*)bbox_pred)[b * NN + i];
        s_gt[i]  = ((const float4*)bbox_gt)[b * NN + i];
        s_lab[i] = labels_gt[b * NN + i];
    }
    __syncthreads();

    for (int idx = threadIdx.x; idx < NN * NN; idx += blockDim.x) {
        int q = idx / NN;
        int g = idx % NN;
        float4 p = s_pr[q];
        float4 t = s_gt[g];

        float pulx = p.x - 0.5f * p.z, puly = p.y - 0.5f * p.w;
        float pdrx = p.x + 0.5f * p.z, pdry = p.y + 0.5f * p.w;
        float gulx = t.x - 0.5f * t.z, guly = t.y - 0.5f * t.w;
        float gdrx = t.x + 0.5f * t.z, gdry = t.y + 0.5f * t.w;

        float iw = fmaxf(fminf(pdrx, gdrx) - fmaxf(pulx, gulx) + 1.0f, 0.0f);
        float ih = fmaxf(fminf(pdry, gdry) - fmaxf(puly, guly) + 1.0f, 0.0f);
        float inter = iw * ih;

        float pw = fmaxf(pdrx - pulx + 1.0f, 0.0f);
        float ph = fmaxf(pdry - puly + 1.0f, 0.0f);
        float gw = fmaxf(gdrx - gulx + 1.0f, 0.0f);
        float gh = fmaxf(gdry - guly + 1.0f, 0.0f);
        float uni = pw * ph + gw * gh - inter;
        float iou = inter / fmaxf(uni, 1e-9f);

        float bw = fmaxf(fmaxf(pdrx, gdrx) - fminf(pulx, gulx) + 1.0f, 0.0f);
        float bh = fmaxf(fmaxf(pdry, gdry) - fminf(puly, guly) + 1.0f, 0.0f);
        float bound = bw * bh;
        float bgr = (bound - uni) / fmaxf(bound, 1e-9f);

        float l1 = fabsf(p.x - t.x) + fabsf(p.y - t.y) +
                   fabsf(p.z - t.z) + fabsf(p.w - t.w);

        float prob = labels_pred[(b * NN + q) * CC + s_lab[g]];

        g_cost[(b * NN + q) * NN + g] = l1 - (iou - bgr) - prob;
    }
}

// ---------------------------------------------------------------------------
// fp32 sortable-key helpers: 32-bit key whose ordering == fp32 ordering.
// ---------------------------------------------------------------------------
__device__ __forceinline__ unsigned f2key(float f)
{
    int b = __float_as_int(f);
    return (unsigned)(b ^ ((b >> 31) | 0x80000000));
}
__device__ __forceinline__ float key2f(unsigned k)
{
    int kk = (int)k;
    return __int_as_float((kk < 0) ? (kk ^ 0x80000000) : ~kk);
}

// ---------------------------------------------------------------------------
// Kernel 2: JV Hungarian, one warp per batch, fp32.
// Phases: column reduction + greedy -> augmenting row reduction (JV phase 2)
// -> Dijkstra augmentation (R10 core) for remaining free rows.
// vs R12: ARR worklist bound fixed (QCAP=416 >= 100 initial + 300 appends),
// append guarded; un-appendable rows just fall through to Dijkstra.
// ---------------------------------------------------------------------------
__global__ void __launch_bounds__(32, 1) hungarian_kernel()
{
    const int b    = blockIdx.x;
    const int lane = threadIdx.x;
    const unsigned FULL   = 0xffffffffu;
    const unsigned KMAX32 = 0xffffffffu;

    __shared__ float  sc[NN * NN];      // 40 KB cost
    __shared__ float  su[NN + 1];       // row duals
    __shared__ float2 cinfo[NN + 1];    // per column: .x = u[sp[j]], .y = bits(sp[j])
    __shared__ int    sp[NN + 1];       // column -> row
    __shared__ int    sway[NN + 1];     // augmenting-path predecessors
    __shared__ int    sargmin[NN + 1];  // column-reduction argmin rows
    __shared__ unsigned char sflag[NN + 1];  // row-assigned flags
    __shared__ int    q[QCAP];          // ARR worklist
    __shared__ int    s_head, s_tail, s_steps;

    const float* gc = g_cost + b * NN * NN;
    for (int t = lane; t < NN * NN; t += 32) sc[t] = gc[t];
    for (int j = lane; j <= NN; j += 32) {
        su[j] = 0.0f; sp[j] = 0; sway[j] = 0; sflag[j] = 0;
    }
    __syncwarp();

    const int jbase = 4 * lane + 1;
    const int coff  = (lane < 25) ? 4 * lane : 96;   // clamped float4 offset
    const unsigned pad = (lane < 25) ? 0u : KMAX32;  // key poison

    // ---- column reduction: v[j] = min_i c[i][j], first-argmin row ----
    float vminf[4] = {INFINITY, INFINITY, INFINITY, INFINITY};
    int   rmin[4]  = {1, 1, 1, 1};
    for (int r = 0; r < NN; r++) {
        float4 cf = *(const float4*)(sc + r * NN + coff);
        float cv[4] = {cf.x, cf.y, cf.z, cf.w};
        #pragma unroll
        for (int s = 0; s < 4; s++)
            if (cv[s] < vminf[s]) { vminf[s] = cv[s]; rmin[s] = r + 1; }
    }
    if (lane < 25) {
        #pragma unroll
        for (int s = 0; s < 4; s++) sargmin[jbase + s] = rmin[s];
    }
    __syncwarp();

    // ---- greedy assignment (serial, lane 0) ----
    if (lane == 0) {
        for (int j = 1; j <= NN; j++) {
            int r = sargmin[j];
            if (!sflag[r]) { sflag[r] = 1; sp[j] = r; }
        }
    }
    __syncwarp();
    if (lane < 25) {
        #pragma unroll
        for (int s = 0; s < 4; s++) {
            int jj = jbase + s;
            cinfo[jj] = make_float2(0.0f, __int_as_float(sp[jj]));
        }
    }
    __syncwarp();

    float v[4];
    #pragma unroll
    for (int s = 0; s < 4; s++) v[s] = vminf[s];

    // ---- ARR worklist: all still-free rows ----
    if (lane == 0) {
        int t = 0;
        for (int i = 1; i <= NN; i++) if (!sflag[i]) q[t++] = i;
        s_head = 0; s_tail = t; s_steps = 0;
    }
    __syncwarp();

    // ---- augmenting row reduction (JV phase 2) ----
    while (true) {
        int h = s_head, t = s_tail, st = s_steps;
        if (h >= t || st >= 300) break;
        int i = q[h];
        __syncwarp();
        if (lane == 0) { s_head = h + 1; s_steps = st + 1; }

        // warp scan of row i: exact min + submin of reduced costs
        const float* crow = sc + (i - 1) * NN;
        float4 cf = *(const float4*)(crow + coff);
        float c4[4] = {cf.x, cf.y, cf.z, cf.w};
        unsigned k[4];
        #pragma unroll
        for (int s = 0; s < 4; s++) k[s] = f2key(c4[s] - v[s]) | pad;

        unsigned lmin = k[0], lsub = KMAX32; int lj = jbase;
        #pragma unroll
        for (int s = 1; s < 4; s++) {
            if (k[s] < lmin) { lsub = lmin; lmin = k[s]; lj = jbase + s; }
            else if (k[s] < lsub) lsub = k[s];
        }
        unsigned m1 = __reduce_min_sync(FULL, lmin);
        float    u1 = key2f(m1);
        unsigned jx = (lmin == m1) ? (unsigned)lj : 127u;
        int      j1 = (int)__reduce_min_sync(FULL, jx);
        unsigned cand = (lmin == m1) ? lsub : lmin;
        unsigned m2 = __reduce_min_sync(FULL, cand);
        float    u2 = key2f(m2);

        bool strict = (m1 < m2);
        int  spj1   = sp[j1];
        bool doassign = strict || (spj1 == 0);
        int  i1 = doassign ? spj1 : 0;
        __syncwarp();

        if (doassign) {
            int sidx  = (j1 - 1) & 3;
            int owner = (j1 - 1) >> 2;
            if (lane == owner) {
                if (strict) v[sidx] -= (u2 - u1);
                float unew = c4[sidx] - v[sidx];
                su[i] = unew;
                cinfo[j1] = make_float2(unew, __int_as_float(i));
            }
            if (lane == 0) {
                sp[j1] = i;
                sflag[i] = 1;
                if (i1) {
                    sflag[i1] = 0;
                    if (t < QCAP) { q[t] = i1; s_tail = t + 1; }
                    // else: i1 stays free and is handled by Dijkstra below
                }
            }
        }
        __syncwarp();
    }
    __syncwarp();

    // ---- augmenting Dijkstra (fp32, R10 core) for remaining free rows ----
    for (int i = 1; i <= NN; i++) {
        if (sflag[i]) continue;        // uniform branch (shared broadcast)

        float    minv[4];
        unsigned mkey[4];
        int      pj[4] = {0, 0, 0, 0};
        float    t4[4];
        #pragma unroll
        for (int s = 0; s < 4; s++) {
            minv[s] = INFINITY; mkey[s] = KMAX32;
            t4[s] = v[s];              // u[i] = 0 at insertion
        }
        unsigned usedm = 0;

        int   j0  = 0;
        int   i0  = i;
        float acc = 0.0f;              // running sum of deltas == u[i]

        while (true) {
            // mark used[j0] (only owner lane matches; never a padding lane)
            #pragma unroll
            for (int s = 0; s < 4; s++)
                if (j0 == jbase + s) { usedm |= 1u << s; mkey[s] = KMAX32; pj[s] = i0; }

            // scan: straight-line, predicated, all-fp32
            const float* crow = sc + (i0 - 1) * NN;
            float4 cf = *(const float4*)(crow + coff);
            float c[4] = {cf.x, cf.y, cf.z, cf.w};
            #pragma unroll
            for (int s = 0; s < 4; s++) {
                if (!((usedm >> s) & 1u)) {
                    float cur = c[s] - t4[s];           // t4 = u[i0] + v[s]
                    unsigned ck = f2key(cur) | pad;
                    if (ck < mkey[s]) { mkey[s] = ck; minv[s] = cur; sway[jbase + s] = j0; }
                }
            }
            // 2-level integer tournament, first-index on ties
            unsigned k01 = mkey[0]; int s01 = 0;
            if (mkey[1] < k01) { k01 = mkey[1]; s01 = 1; }
            unsigned k23 = mkey[2]; int s23 = 2;
            if (mkey[3] < k23) { k23 = mkey[3]; s23 = 3; }
            unsigned bkey = k01; int sb = s01;
            if (k23 < k01) { bkey = k23; sb = s23; }
            int bj = jbase + sb;

            // warp argmin: REDUX on 32-bit key (delta = exact inverse), then
            // REDUX on index among exact-key matchers (lowest-j tie-break)
            unsigned m1 = __reduce_min_sync(FULL, bkey);
            float delta = key2f(m1);
            unsigned jx = (bkey == m1) ? (unsigned)bj : 127u;
            int j1 = (int)__reduce_min_sync(FULL, jx);

            // dual updates (su addresses lane-owned; never padding lanes)
            #pragma unroll
            for (int s = 0; s < 4; s++) {
                if ((usedm >> s) & 1u) {
                    su[pj[s]] += delta;
                    v[s] -= delta;
                } else {
                    minv[s] -= delta;
                    mkey[s] = f2key(minv[s]) | pad;
                }
            }
            acc += delta;

            // single 64-bit LDS: {u[sp[j1]], sp[j1]} — frozen during the run
            float2 ci = cinfo[j1];
            int i0n = __float_as_int(ci.y);
            if (i0n == 0) { j0 = j1; break; }
            j0 = j1;
            i0 = i0n;
            // hoisted t for next iteration (off the LDS critical path)
            #pragma unroll
            for (int s = 0; s < 4; s++) t4[s] = ci.x + v[s];
        }

        // augment (serial, lane 0); write back u[i] once
        __syncwarp();
        if (lane == 0) {
            su[i]  = acc;
            sp[0]  = i;
            int jj = j0;
            while (jj) { int jn = sway[jj]; sp[jj] = sp[jn]; jj = jn; }
        }
        __syncwarp();

        // refresh cached {u,row} for used columns AND the break column j0
        #pragma unroll
        for (int s = 0; s < 4; s++) {
            int jj = jbase + s;
            if (((usedm >> s) & 1u) || (jj == j0)) {
                int r = sp[jj];
                cinfo[jj] = make_float2(su[r], __int_as_float(r));
            }
        }
        __syncwarp();
    }

    for (int j = lane + 1; j <= NN; j += 32)
        g_col[b * NN + (sp[j] - 1)] = j - 1;
}

// ---------------------------------------------------------------------------
// Kernel 3: per-batch losses.
// ---------------------------------------------------------------------------
__global__ void loss_kernel(const float* __restrict__ bbox_pred,
                            const float* __restrict__ labels_pred,
                            const float* __restrict__ bbox_gt,
                            const int*   __restrict__ labels_gt)
{
    int b   = blockIdx.x;
    int tid = threadIdx.x;  // 128

    double nll_sum = 0.0, reg_sum = 0.0, giou_sum = 0.0;

    for (int q2 = tid; q2 < NN; q2 += blockDim.x) {
        int cg  = g_col[b * NN + q2];
        int lab = labels_gt[b * NN + cg];

        const float* pr = labels_pred + (size_t)(b * NN + q2) * CC;
        double se = 0.0;
        float  plab = 0.0f;
        for (int c = 0; c < CC; c++) {
            float pc = fminf(fmaxf(pr[c], 1e-7f), 1.0f - 1e-7f);
            se += (double)pc;
            if (c == lab) plab = pc;
        }
        nll_sum += log(se) - (double)logf(plab);

        float4 p = ((const float4*)bbox_pred)[b * NN + q2];
        float4 t = ((const float4*)bbox_gt)[b * NN + cg];
        reg_sum += (double)(fabsf(p.x - t.x) + fabsf(p.y - t.y) +
                            fabsf(p.z - t.z) + fabsf(p.w - t.w));

        float4 g = ((const float4*)bbox_gt)[b * NN + q2];
        float pulx = p.x - 0.5f * p.z, puly = p.y - 0.5f * p.w;
        float pdrx = p.x + 0.5f * p.z, pdry = p.y + 0.5f * p.w;
        float gulx = g.x - 0.5f * g.z, guly = g.y - 0.5f * g.w;
        float gdrx = g.x + 0.5f * g.z, gdry = g.y + 0.5f * g.w;
        float iw = fmaxf(fminf(pdrx, gdrx) - fmaxf(pulx, gulx) + 1.0f, 0.0f);
        float ih = fmaxf(fminf(pdry, gdry) - fmaxf(puly, guly) + 1.0f, 0.0f);
        float inter = iw * ih;
        float pw = fmaxf(pdrx - pulx + 1.0f, 0.0f);
        float ph = fmaxf(pdry - puly + 1.0f, 0.0f);
        float gw = fmaxf(gdrx - gulx + 1.0f, 0.0f);
        float gh = fmaxf(gdry - guly + 1.0f, 0.0f);
        float uni = pw * ph + gw * gh - inter;
        float iou = inter / fmaxf(uni, 1e-9f);
        float bw = fmaxf(fmaxf(pdrx, gdrx) - fminf(pulx, gulx) + 1.0f, 0.0f);
        float bh = fmaxf(fmaxf(pdry, gdry) - fminf(puly, guly) + 1.0f, 0.0f);
        float bound = bw * bh;
        float bgr = (bound - uni) / fmaxf(bound, 1e-9f);
        giou_sum += (double)(iou - bgr);
    }

    __shared__ double s0[128], s1[128], s2[128];
    s0[tid] = nll_sum; s1[tid] = reg_sum; s2[tid] = giou_sum;
    __syncthreads();
    for (int s = 64; s; s >>= 1) {
        if (tid < s) { s0[tid] += s0[tid + s]; s1[tid] += s1[tid + s]; s2[tid] += s2[tid + s]; }
        __syncthreads();
    }
    if (tid == 0) {
        double per = s0[0] / NN + 5.0 * (s1[0] / (NN * 4.0)) + 2.0 * (s2[0] / NN);
        g_partial[b] = per;
    }
}

__global__ void final_kernel(float* __restrict__ out)
{
    double s = 0.0;
    for (int b = 0; b < BB; b++) s += g_partial[b];
    out[0] = (float)s;
}

// ---------------------------------------------------------------------------
extern "C" void kernel_launch(void* const* d_in, const int* in_sizes, int n_in,
                              void* d_out, int out_size)
{
    const float* bbox_pred   = (const float*)d_in[0];
    const float* labels_pred = (const float*)d_in[1];
    const float* bbox_gt     = (const float*)d_in[2];
    const int*   labels_gt   = (const int*)d_in[3];

    cost_kernel<<<BB, 256>>>(bbox_pred, labels_pred, bbox_gt, labels_gt);
    hungarian_kernel<<<BB, 32>>>();
    loss_kernel<<<BB, 128>>>(bbox_pred, labels_pred, bbox_gt, labels_gt);
    final_kernel<<<1, 1>>>((float*)d_out);
}

// round 15
// speedup vs baseline: 1.4013x; 1.0701x over previous
#include <cuda_runtime.h>
#include <math.h>

#define BB 16
#define NN 100
#define CC 100
#define QCAP 416   // >= max initial free rows (100) + max appends (300 steps)

__device__ float  g_cost[BB * NN * NN];
__device__ int    g_col[BB * NN];
__device__ double g_partial[BB];

// ---------------------------------------------------------------------------
// Kernel 1: cost matrix, fp32 in the reference's exact op order.
// ---------------------------------------------------------------------------
__global__ void cost_kernel(const float* __restrict__ bbox_pred,
                            const float* __restrict__ labels_pred,
                            const float* __restrict__ bbox_gt,
                            const int*   __restrict__ labels_gt)
{
    int b = blockIdx.x;
    __shared__ float4 s_pr[NN];
    __shared__ float4 s_gt[NN];
    __shared__ int    s_lab[NN];
    for (int i = threadIdx.x; i < NN; i += blockDim.x) {
        s_pr[i]  = ((const float4*)bbox_pred)[b * NN + i];
        s_gt[i]  = ((const float4*)bbox_gt)[b * NN + i];
        s_lab[i] = labels_gt[b * NN + i];
    }
    __syncthreads();

    for (int idx = threadIdx.x; idx < NN * NN; idx += blockDim.x) {
        int q = idx / NN;
        int g = idx % NN;
        float4 p = s_pr[q];
        float4 t = s_gt[g];

        float pulx = p.x - 0.5f * p.z, puly = p.y - 0.5f * p.w;
        float pdrx = p.x + 0.5f * p.z, pdry = p.y + 0.5f * p.w;
        float gulx = t.x - 0.5f * t.z, guly = t.y - 0.5f * t.w;
        float gdrx = t.x + 0.5f * t.z, gdry = t.y + 0.5f * t.w;

        float iw = fmaxf(fminf(pdrx, gdrx) - fmaxf(pulx, gulx) + 1.0f, 0.0f);
        float ih = fmaxf(fminf(pdry, gdry) - fmaxf(puly, guly) + 1.0f, 0.0f);
        float inter = iw * ih;

        float pw = fmaxf(pdrx - pulx + 1.0f, 0.0f);
        float ph = fmaxf(pdry - puly + 1.0f, 0.0f);
        float gw = fmaxf(gdrx - gulx + 1.0f, 0.0f);
        float gh = fmaxf(gdry - guly + 1.0f, 0.0f);
        float uni = pw * ph + gw * gh - inter;
        float iou = inter / fmaxf(uni, 1e-9f);

        float bw = fmaxf(fmaxf(pdrx, gdrx) - fminf(pulx, gulx) + 1.0f, 0.0f);
        float bh = fmaxf(fmaxf(pdry, gdry) - fminf(puly, guly) + 1.0f, 0.0f);
        float bound = bw * bh;
        float bgr = (bound - uni) / fmaxf(bound, 1e-9f);

        float l1 = fabsf(p.x - t.x) + fabsf(p.y - t.y) +
                   fabsf(p.z - t.z) + fabsf(p.w - t.w);

        float prob = labels_pred[(b * NN + q) * CC + s_lab[g]];

        g_cost[(b * NN + q) * NN + g] = l1 - (iou - bgr) - prob;
    }
}

// ---------------------------------------------------------------------------
// fp32 sortable-key helpers: 32-bit key whose ordering == fp32 ordering.
// ---------------------------------------------------------------------------
__device__ __forceinline__ unsigned f2key(float f)
{
    int b = __float_as_int(f);
    return (unsigned)(b ^ ((b >> 31) | 0x80000000));
}
__device__ __forceinline__ float key2f(unsigned k)
{
    int kk = (int)k;
    return __int_as_float((kk < 0) ? (kk ^ 0x80000000) : ~kk);
}

// ---------------------------------------------------------------------------
// Kernel 2: JV Hungarian, one warp per batch, fp32.
// Phases: column reduction + greedy -> augmenting row reduction (JV phase 2)
// -> Dijkstra augmentation (R10 core) for remaining free rows.
// vs R14: ARR submin fixed for CROSS-LANE duplicate minima. If the row min
// occurs in >=2 columns, the true submin equals the min, so strict must be
// false (no v tightening). Previously each min-holding lane contributed its
// lane-local submin, making m2 > m1 and wrongly tightening v by O(gap) --
// the likely source of R14's rel_err jump to 7.9e-4.
// ---------------------------------------------------------------------------
__global__ void __launch_bounds__(32, 1) hungarian_kernel()
{
    const int b    = blockIdx.x;
    const int lane = threadIdx.x;
    const unsigned FULL   = 0xffffffffu;
    const unsigned KMAX32 = 0xffffffffu;

    __shared__ float  sc[NN * NN];      // 40 KB cost
    __shared__ float  su[NN + 1];       // row duals
    __shared__ float2 cinfo[NN + 1];    // per column: .x = u[sp[j]], .y = bits(sp[j])
    __shared__ int    sp[NN + 1];       // column -> row
    __shared__ int    sway[NN + 1];     // augmenting-path predecessors
    __shared__ int    sargmin[NN + 1];  // column-reduction argmin rows
    __shared__ unsigned char sflag[NN + 1];  // row-assigned flags
    __shared__ int    q[QCAP];          // ARR worklist
    __shared__ int    s_head, s_tail, s_steps;

    const float* gc = g_cost + b * NN * NN;
    for (int t = lane; t < NN * NN; t += 32) sc[t] = gc[t];
    for (int j = lane; j <= NN; j += 32) {
        su[j] = 0.0f; sp[j] = 0; sway[j] = 0; sflag[j] = 0;
    }
    __syncwarp();

    const int jbase = 4 * lane + 1;
    const int coff  = (lane < 25) ? 4 * lane : 96;   // clamped float4 offset
    const unsigned pad = (lane < 25) ? 0u : KMAX32;  // key poison

    // ---- column reduction: v[j] = min_i c[i][j], first-argmin row ----
    float vminf[4] = {INFINITY, INFINITY, INFINITY, INFINITY};
    int   rmin[4]  = {1, 1, 1, 1};
    for (int r = 0; r < NN; r++) {
        float4 cf = *(const float4*)(sc + r * NN + coff);
        float cv[4] = {cf.x, cf.y, cf.z, cf.w};
        #pragma unroll
        for (int s = 0; s < 4; s++)
            if (cv[s] < vminf[s]) { vminf[s] = cv[s]; rmin[s] = r + 1; }
    }
    if (lane < 25) {
        #pragma unroll
        for (int s = 0; s < 4; s++) sargmin[jbase + s] = rmin[s];
    }
    __syncwarp();

    // ---- greedy assignment (serial, lane 0) ----
    if (lane == 0) {
        for (int j = 1; j <= NN; j++) {
            int r = sargmin[j];
            if (!sflag[r]) { sflag[r] = 1; sp[j] = r; }
        }
    }
    __syncwarp();
    if (lane < 25) {
        #pragma unroll
        for (int s = 0; s < 4; s++) {
            int jj = jbase + s;
            cinfo[jj] = make_float2(0.0f, __int_as_float(sp[jj]));
        }
    }
    __syncwarp();

    float v[4];
    #pragma unroll
    for (int s = 0; s < 4; s++) v[s] = vminf[s];

    // ---- ARR worklist: all still-free rows ----
    if (lane == 0) {
        int t = 0;
        for (int i = 1; i <= NN; i++) if (!sflag[i]) q[t++] = i;
        s_head = 0; s_tail = t; s_steps = 0;
    }
    __syncwarp();

    // ---- augmenting row reduction (JV phase 2) ----
    while (true) {
        int h = s_head, t = s_tail, st = s_steps;
        if (h >= t || st >= 300) break;
        int i = q[h];
        __syncwarp();
        if (lane == 0) { s_head = h + 1; s_steps = st + 1; }

        // warp scan of row i: exact min + submin of reduced costs
        const float* crow = sc + (i - 1) * NN;
        float4 cf = *(const float4*)(crow + coff);
        float c4[4] = {cf.x, cf.y, cf.z, cf.w};
        unsigned k[4];
        #pragma unroll
        for (int s = 0; s < 4; s++) k[s] = f2key(c4[s] - v[s]) | pad;

        unsigned lmin = k[0], lsub = KMAX32; int lj = jbase;
        #pragma unroll
        for (int s = 1; s < 4; s++) {
            if (k[s] < lmin) { lsub = lmin; lmin = k[s]; lj = jbase + s; }
            else if (k[s] < lsub) lsub = k[s];
        }
        unsigned m1 = __reduce_min_sync(FULL, lmin);
        float    u1 = key2f(m1);
        unsigned jx = (lmin == m1) ? (unsigned)lj : 127u;
        int      j1 = (int)__reduce_min_sync(FULL, jx);
        unsigned cand = (lmin == m1) ? lsub : lmin;
        unsigned m2 = __reduce_min_sync(FULL, cand);
        // cross-lane duplicate min: true submin == min (within-lane dup is
        // already captured by lsub). Without this, m2 > m1 wrongly triggers
        // the strict path and over-tightens v.
        int ndup = __popc(__ballot_sync(FULL, lmin == m1));
        if (ndup >= 2) m2 = m1;
        float    u2 = key2f(m2);

        bool strict = (m1 < m2);
        int  spj1   = sp[j1];
        bool doassign = strict || (spj1 == 0);
        int  i1 = doassign ? spj1 : 0;
        __syncwarp();

        if (doassign) {
            int sidx  = (j1 - 1) & 3;
            int owner = (j1 - 1) >> 2;
            if (lane == owner) {
                if (strict) v[sidx] -= (u2 - u1);
                float unew = c4[sidx] - v[sidx];
                su[i] = unew;
                cinfo[j1] = make_float2(unew, __int_as_float(i));
            }
            if (lane == 0) {
                sp[j1] = i;
                sflag[i] = 1;
                if (i1) {
                    sflag[i1] = 0;
                    if (t < QCAP) { q[t] = i1; s_tail = t + 1; }
                    // else: i1 stays free and is handled by Dijkstra below
                }
            }
        }
        __syncwarp();
    }
    __syncwarp();

    // ---- augmenting Dijkstra (fp32, R10 core) for remaining free rows ----
    for (int i = 1; i <= NN; i++) {
        if (sflag[i]) continue;        // uniform branch (shared broadcast)

        float    minv[4];
        unsigned mkey[4];
        int      pj[4] = {0, 0, 0, 0};
        float    t4[4];
        #pragma unroll
        for (int s = 0; s < 4; s++) {
            minv[s] = INFINITY; mkey[s] = KMAX32;
            t4[s] = v[s];              // u[i] = 0 at insertion
        }
        unsigned usedm = 0;

        int   j0  = 0;
        int   i0  = i;
        float acc = 0.0f;              // running sum of deltas == u[i]

        while (true) {
            // mark used[j0] (only owner lane matches; never a padding lane)
            #pragma unroll
            for (int s = 0; s < 4; s++)
                if (j0 == jbase + s) { usedm |= 1u << s; mkey[s] = KMAX32; pj[s] = i0; }

            // scan: straight-line, predicated, all-fp32
            const float* crow = sc + (i0 - 1) * NN;
            float4 cf = *(const float4*)(crow + coff);
            float c[4] = {cf.x, cf.y, cf.z, cf.w};
            #pragma unroll
            for (int s = 0; s < 4; s++) {
                if (!((usedm >> s) & 1u)) {
                    float cur = c[s] - t4[s];           // t4 = u[i0] + v[s]
                    unsigned ck = f2key(cur) | pad;
                    if (ck < mkey[s]) { mkey[s] = ck; minv[s] = cur; sway[jbase + s] = j0; }
                }
            }
            // 2-level integer tournament, first-index on ties
            unsigned k01 = mkey[0]; int s01 = 0;
            if (mkey[1] < k01) { k01 = mkey[1]; s01 = 1; }
            unsigned k23 = mkey[2]; int s23 = 2;
            if (mkey[3] < k23) { k23 = mkey[3]; s23 = 3; }
            unsigned bkey = k01; int sb = s01;
            if (k23 < k01) { bkey = k23; sb = s23; }
            int bj = jbase + sb;

            // warp argmin: REDUX on 32-bit key (delta = exact inverse), then
            // REDUX on index among exact-key matchers (lowest-j tie-break)
            unsigned m1 = __reduce_min_sync(FULL, bkey);
            float delta = key2f(m1);
            unsigned jx = (bkey == m1) ? (unsigned)bj : 127u;
            int j1 = (int)__reduce_min_sync(FULL, jx);

            // dual updates (su addresses lane-owned; never padding lanes)
            #pragma unroll
            for (int s = 0; s < 4; s++) {
                if ((usedm >> s) & 1u) {
                    su[pj[s]] += delta;
                    v[s] -= delta;
                } else {
                    minv[s] -= delta;
                    mkey[s] = f2key(minv[s]) | pad;
                }
            }
            acc += delta;

            // single 64-bit LDS: {u[sp[j1]], sp[j1]} — frozen during the run
            float2 ci = cinfo[j1];
            int i0n = __float_as_int(ci.y);
            if (i0n == 0) { j0 = j1; break; }
            j0 = j1;
            i0 = i0n;
            // hoisted t for next iteration (off the LDS critical path)
            #pragma unroll
            for (int s = 0; s < 4; s++) t4[s] = ci.x + v[s];
        }

        // augment (serial, lane 0); write back u[i] once
        __syncwarp();
        if (lane == 0) {
            su[i]  = acc;
            sp[0]  = i;
            int jj = j0;
            while (jj) { int jn = sway[jj]; sp[jj] = sp[jn]; jj = jn; }
        }
        __syncwarp();

        // refresh cached {u,row} for used columns AND the break column j0
        #pragma unroll
        for (int s = 0; s < 4; s++) {
            int jj = jbase + s;
            if (((usedm >> s) & 1u) || (jj == j0)) {
                int r = sp[jj];
                cinfo[jj] = make_float2(su[r], __int_as_float(r));
            }
        }
        __syncwarp();
    }

    for (int j = lane + 1; j <= NN; j += 32)
        g_col[b * NN + (sp[j] - 1)] = j - 1;
}

// ---------------------------------------------------------------------------
// Kernel 3: per-batch losses.
// ---------------------------------------------------------------------------
__global__ void loss_kernel(const float* __restrict__ bbox_pred,
                            const float* __restrict__ labels_pred,
                            const float* __restrict__ bbox_gt,
                            const int*   __restrict__ labels_gt)
{
    int b   = blockIdx.x;
    int tid = threadIdx.x;  // 128

    double nll_sum = 0.0, reg_sum = 0.0, giou_sum = 0.0;

    for (int q2 = tid; q2 < NN; q2 += blockDim.x) {
        int cg  = g_col[b * NN + q2];
        int lab = labels_gt[b * NN + cg];

        const float* pr = labels_pred + (size_t)(b * NN + q2) * CC;
        double se = 0.0;
        float  plab = 0.0f;
        for (int c = 0; c < CC; c++) {
            float pc = fminf(fmaxf(pr[c], 1e-7f), 1.0f - 1e-7f);
            se += (double)pc;
            if (c == lab) plab = pc;
        }
        nll_sum += log(se) - (double)logf(plab);

        float4 p = ((const float4*)bbox_pred)[b * NN + q2];
        float4 t = ((const float4*)bbox_gt)[b * NN + cg];
        reg_sum += (double)(fabsf(p.x - t.x) + fabsf(p.y - t.y) +
                            fabsf(p.z - t.z) + fabsf(p.w - t.w));

        float4 g = ((const float4*)bbox_gt)[b * NN + q2];
        float pulx = p.x - 0.5f * p.z, puly = p.y - 0.5f * p.w;
        float pdrx = p.x + 0.5f * p.z, pdry = p.y + 0.5f * p.w;
        float gulx = g.x - 0.5f * g.z, guly = g.y - 0.5f * g.w;
        float gdrx = g.x + 0.5f * g.z, gdry = g.y + 0.5f * g.w;
        float iw = fmaxf(fminf(pdrx, gdrx) - fmaxf(pulx, gulx) + 1.0f, 0.0f);
        float ih = fmaxf(fminf(pdry, gdry) - fmaxf(puly, guly) + 1.0f, 0.0f);
        float inter = iw * ih;
        float pw = fmaxf(pdrx - pulx + 1.0f, 0.0f);
        float ph = fmaxf(pdry - puly + 1.0f, 0.0f);
        float gw = fmaxf(gdrx - gulx + 1.0f, 0.0f);
        float gh = fmaxf(gdry - guly + 1.0f, 0.0f);
        float uni = pw * ph + gw * gh - inter;
        float iou = inter / fmaxf(uni, 1e-9f);
        float bw = fmaxf(fmaxf(pdrx, gdrx) - fminf(pulx, gulx) + 1.0f, 0.0f);
        float bh = fmaxf(fmaxf(pdry, gdry) - fminf(puly, guly) + 1.0f, 0.0f);
        float bound = bw * bh;
        float bgr = (bound - uni) / fmaxf(bound, 1e-9f);
        giou_sum += (double)(iou - bgr);
    }

    __shared__ double s0[128], s1[128], s2[128];
    s0[tid] = nll_sum; s1[tid] = reg_sum; s2[tid] = giou_sum;
    __syncthreads();
    for (int s = 64; s; s >>= 1) {
        if (tid < s) { s0[tid] += s0[tid + s]; s1[tid] += s1[tid + s]; s2[tid] += s2[tid + s]; }
        __syncthreads();
    }
    if (tid == 0) {
        double per = s0[0] / NN + 5.0 * (s1[0] / (NN * 4.0)) + 2.0 * (s2[0] / NN);
        g_partial[b] = per;
    }
}

__global__ void final_kernel(float* __restrict__ out)
{
    double s = 0.0;
    for (int b = 0; b < BB; b++) s += g_partial[b];
    out[0] = (float)s;
}

// ---------------------------------------------------------------------------
extern "C" void kernel_launch(void* const* d_in, const int* in_sizes, int n_in,
                              void* d_out, int out_size)
{
    const float* bbox_pred   = (const float*)d_in[0];
    const float* labels_pred = (const float*)d_in[1];
    const float* bbox_gt     = (const float*)d_in[2];
    const int*   labels_gt   = (const int*)d_in[3];

    cost_kernel<<<BB, 256>>>(bbox_pred, labels_pred, bbox_gt, labels_gt);
    hungarian_kernel<<<BB, 32>>>();
    loss_kernel<<<BB, 128>>>(bbox_pred, labels_pred, bbox_gt, labels_gt);
    final_kernel<<<1, 1>>>((float*)d_out);
}

// round 16
// speedup vs baseline: 1.5230x; 1.0868x over previous
#include <cuda_runtime.h>
#include <math.h>

#define BB 16
#define NN 100
#define CC 100
#define QCAP 416   // >= max initial free rows (100) + max appends (300 steps)

__device__ float  g_cost[BB * NN * NN];
__device__ int    g_col[BB * NN];
__device__ double g_partial[BB];

// ---------------------------------------------------------------------------
// Kernel 1: cost matrix, fp32 in the reference's exact op order.
// ---------------------------------------------------------------------------
__global__ void cost_kernel(const float* __restrict__ bbox_pred,
                            const float* __restrict__ labels_pred,
                            const float* __restrict__ bbox_gt,
                            const int*   __restrict__ labels_gt)
{
    int b = blockIdx.x;
    __shared__ float4 s_pr[NN];
    __shared__ float4 s_gt[NN];
    __shared__ int    s_lab[NN];
    for (int i = threadIdx.x; i < NN; i += blockDim.x) {
        s_pr[i]  = ((const float4*)bbox_pred)[b * NN + i];
        s_gt[i]  = ((const float4*)bbox_gt)[b * NN + i];
        s_lab[i] = labels_gt[b * NN + i];
    }
    __syncthreads();

    for (int idx = threadIdx.x; idx < NN * NN; idx += blockDim.x) {
        int q = idx / NN;
        int g = idx % NN;
        float4 p = s_pr[q];
        float4 t = s_gt[g];

        float pulx = p.x - 0.5f * p.z, puly = p.y - 0.5f * p.w;
        float pdrx = p.x + 0.5f * p.z, pdry = p.y + 0.5f * p.w;
        float gulx = t.x - 0.5f * t.z, guly = t.y - 0.5f * t.w;
        float gdrx = t.x + 0.5f * t.z, gdry = t.y + 0.5f * t.w;

        float iw = fmaxf(fminf(pdrx, gdrx) - fmaxf(pulx, gulx) + 1.0f, 0.0f);
        float ih = fmaxf(fminf(pdry, gdry) - fmaxf(puly, guly) + 1.0f, 0.0f);
        float inter = iw * ih;

        float pw = fmaxf(pdrx - pulx + 1.0f, 0.0f);
        float ph = fmaxf(pdry - puly + 1.0f, 0.0f);
        float gw = fmaxf(gdrx - gulx + 1.0f, 0.0f);
        float gh = fmaxf(gdry - guly + 1.0f, 0.0f);
        float uni = pw * ph + gw * gh - inter;
        float iou = inter / fmaxf(uni, 1e-9f);

        float bw = fmaxf(fmaxf(pdrx, gdrx) - fminf(pulx, gulx) + 1.0f, 0.0f);
        float bh = fmaxf(fmaxf(pdry, gdry) - fminf(puly, guly) + 1.0f, 0.0f);
        float bound = bw * bh;
        float bgr = (bound - uni) / fmaxf(bound, 1e-9f);

        float l1 = fabsf(p.x - t.x) + fabsf(p.y - t.y) +
                   fabsf(p.z - t.z) + fabsf(p.w - t.w);

        float prob = labels_pred[(b * NN + q) * CC + s_lab[g]];

        g_cost[(b * NN + q) * NN + g] = l1 - (iou - bgr) - prob;
    }
}

// ---------------------------------------------------------------------------
// fp32 sortable-key helpers: 32-bit key whose ordering == fp32 ordering.
// ---------------------------------------------------------------------------
__device__ __forceinline__ unsigned f2key(float f)
{
    int b = __float_as_int(f);
    return (unsigned)(b ^ ((b >> 31) | 0x80000000));
}
__device__ __forceinline__ float key2f(unsigned k)
{
    int kk = (int)k;
    return __int_as_float((kk < 0) ? (kk ^ 0x80000000) : ~kk);
}

// ---------------------------------------------------------------------------
// Kernel 2: JV Hungarian, one warp per batch, fp32.
// Phases: column reduction + greedy -> augmenting row reduction (with the
// R15 cross-lane duplicate-min fix) -> Dijkstra augmentation.
// vs R15: Dijkstra rewritten in distance-label form. d[j] = absolute path
// distance; delta = min d (monotone); scan uses cur = c - ((u[i0]-delta)+v).
// ALL per-iteration dual updates are gone -- deferred to row end via the
// telescoped sums: dd = deltaF - d[j] per used column (v[j] -= dd,
// su[old_row] = cinfo.x + dd), su[i] = deltaF. Algebraically identical to
// the incremental scheme with less rounding; assignment unchanged.
// ---------------------------------------------------------------------------
__global__ void __launch_bounds__(32, 1) hungarian_kernel()
{
    const int b    = blockIdx.x;
    const int lane = threadIdx.x;
    const unsigned FULL   = 0xffffffffu;
    const unsigned KMAX32 = 0xffffffffu;

    __shared__ float  sc[NN * NN];      // 40 KB cost
    __shared__ float  su[NN + 1];       // row duals
    __shared__ float2 cinfo[NN + 1];    // per column: .x = u[sp[j]], .y = bits(sp[j])
    __shared__ int    sp[NN + 1];       // column -> row
    __shared__ int    sway[NN + 1];     // augmenting-path predecessors
    __shared__ int    sargmin[NN + 1];  // column-reduction argmin rows
    __shared__ unsigned char sflag[NN + 1];  // row-assigned flags
    __shared__ int    q[QCAP];          // ARR worklist
    __shared__ int    s_head, s_tail, s_steps;

    const float* gc = g_cost + b * NN * NN;
    for (int t = lane; t < NN * NN; t += 32) sc[t] = gc[t];
    for (int j = lane; j <= NN; j += 32) {
        su[j] = 0.0f; sp[j] = 0; sway[j] = 0; sflag[j] = 0;
    }
    __syncwarp();

    const int jbase = 4 * lane + 1;
    const int coff  = (lane < 25) ? 4 * lane : 96;   // clamped float4 offset
    const unsigned pad = (lane < 25) ? 0u : KMAX32;  // key poison

    // ---- column reduction: v[j] = min_i c[i][j], first-argmin row ----
    float vminf[4] = {INFINITY, INFINITY, INFINITY, INFINITY};
    int   rmin[4]  = {1, 1, 1, 1};
    for (int r = 0; r < NN; r++) {
        float4 cf = *(const float4*)(sc + r * NN + coff);
        float cv[4] = {cf.x, cf.y, cf.z, cf.w};
        #pragma unroll
        for (int s = 0; s < 4; s++)
            if (cv[s] < vminf[s]) { vminf[s] = cv[s]; rmin[s] = r + 1; }
    }
    if (lane < 25) {
        #pragma unroll
        for (int s = 0; s < 4; s++) sargmin[jbase + s] = rmin[s];
    }
    __syncwarp();

    // ---- greedy assignment (serial, lane 0) ----
    if (lane == 0) {
        for (int j = 1; j <= NN; j++) {
            int r = sargmin[j];
            if (!sflag[r]) { sflag[r] = 1; sp[j] = r; }
        }
    }
    __syncwarp();
    if (lane < 25) {
        #pragma unroll
        for (int s = 0; s < 4; s++) {
            int jj = jbase + s;
            cinfo[jj] = make_float2(0.0f, __int_as_float(sp[jj]));
        }
    }
    __syncwarp();

    float v[4];
    #pragma unroll
    for (int s = 0; s < 4; s++) v[s] = vminf[s];

    // ---- ARR worklist: all still-free rows ----
    if (lane == 0) {
        int t = 0;
        for (int i = 1; i <= NN; i++) if (!sflag[i]) q[t++] = i;
        s_head = 0; s_tail = t; s_steps = 0;
    }
    __syncwarp();

    // ---- augmenting row reduction (JV phase 2) ----
    while (true) {
        int h = s_head, t = s_tail, st = s_steps;
        if (h >= t || st >= 300) break;
        int i = q[h];
        __syncwarp();
        if (lane == 0) { s_head = h + 1; s_steps = st + 1; }

        // warp scan of row i: exact min + submin of reduced costs
        const float* crow = sc + (i - 1) * NN;
        float4 cf = *(const float4*)(crow + coff);
        float c4[4] = {cf.x, cf.y, cf.z, cf.w};
        unsigned k[4];
        #pragma unroll
        for (int s = 0; s < 4; s++) k[s] = f2key(c4[s] - v[s]) | pad;

        unsigned lmin = k[0], lsub = KMAX32; int lj = jbase;
        #pragma unroll
        for (int s = 1; s < 4; s++) {
            if (k[s] < lmin) { lsub = lmin; lmin = k[s]; lj = jbase + s; }
            else if (k[s] < lsub) lsub = k[s];
        }
        unsigned m1 = __reduce_min_sync(FULL, lmin);
        float    u1 = key2f(m1);
        unsigned jx = (lmin == m1) ? (unsigned)lj : 127u;
        int      j1 = (int)__reduce_min_sync(FULL, jx);
        unsigned cand = (lmin == m1) ? lsub : lmin;
        unsigned m2 = __reduce_min_sync(FULL, cand);
        // cross-lane duplicate min: true submin == min => strict must be false
        int ndup = __popc(__ballot_sync(FULL, lmin == m1));
        if (ndup >= 2) m2 = m1;
        float    u2 = key2f(m2);

        bool strict = (m1 < m2);
        int  spj1   = sp[j1];
        bool doassign = strict || (spj1 == 0);
        int  i1 = doassign ? spj1 : 0;
        __syncwarp();

        if (doassign) {
            int sidx  = (j1 - 1) & 3;
            int owner = (j1 - 1) >> 2;
            if (lane == owner) {
                if (strict) v[sidx] -= (u2 - u1);
                float unew = c4[sidx] - v[sidx];
                su[i] = unew;
                cinfo[j1] = make_float2(unew, __int_as_float(i));
            }
            if (lane == 0) {
                sp[j1] = i;
                sflag[i] = 1;
                if (i1) {
                    sflag[i1] = 0;
                    if (t < QCAP) { q[t] = i1; s_tail = t + 1; }
                    // else: i1 stays free and is handled by Dijkstra below
                }
            }
        }
        __syncwarp();
    }
    __syncwarp();

    // ---- Dijkstra augmentation (distance-label form) for remaining rows ----
    for (int i = 1; i <= NN; i++) {
        if (sflag[i]) continue;        // uniform branch (shared broadcast)

        float    d[4];                 // absolute path distances (frozen at mark)
        unsigned dkey[4];
        float    t4[4];
        #pragma unroll
        for (int s = 0; s < 4; s++) {
            d[s] = INFINITY; dkey[s] = KMAX32;
            t4[s] = v[s];              // u[i]=0, delta=0 for the first scan
        }
        unsigned usedm = 0;

        int   j0 = 0;                  // predecessor column for sway
        int   i0 = i;
        float deltaF;

        while (true) {
            // scan row i0: cur = delta + c - u[i0] - v = c - t4 (absolute)
            const float* crow = sc + (i0 - 1) * NN;
            float4 cf = *(const float4*)(crow + coff);
            float c[4] = {cf.x, cf.y, cf.z, cf.w};
            #pragma unroll
            for (int s = 0; s < 4; s++) {
                if (!((usedm >> s) & 1u)) {
                    float cur = c[s] - t4[s];
                    unsigned ck = f2key(cur) | pad;
                    if (ck < dkey[s]) { dkey[s] = ck; d[s] = cur; sway[jbase + s] = j0; }
                }
            }
            // 2-level integer tournament, first-index on ties
            unsigned k01 = dkey[0]; int s01 = 0;
            if (dkey[1] < k01) { k01 = dkey[1]; s01 = 1; }
            unsigned k23 = dkey[2]; int s23 = 2;
            if (dkey[3] < k23) { k23 = dkey[3]; s23 = 3; }
            unsigned bkey = k01; int sb = s01;
            if (k23 < k01) { bkey = k23; sb = s23; }
            int bj = jbase + sb;

            // warp argmin: delta = absolute distance of the winner
            unsigned m1 = __reduce_min_sync(FULL, bkey);
            float delta = key2f(m1);
            unsigned jx = (bkey == m1) ? (unsigned)bj : 127u;
            int j1 = (int)__reduce_min_sync(FULL, jx);

            float2 ci = cinfo[j1];
            int i0n = __float_as_int(ci.y);
            if (i0n == 0) { j0 = j1; deltaF = delta; break; }  // j1 NOT marked

            // mark j1 used (owner lane; d[s] keeps its frozen value == delta)
            #pragma unroll
            for (int s = 0; s < 4; s++)
                if (j1 == jbase + s) { usedm |= 1u << s; dkey[s] = KMAX32; }

            j0 = j1;
            i0 = i0n;
            float base = ci.x - delta;          // u[i0] - delta
            #pragma unroll
            for (int s = 0; s < 4; s++) t4[s] = base + v[s];
        }

        // augment (serial, lane 0); u[i] = deltaF
        __syncwarp();
        if (lane == 0) {
            su[i]  = deltaF;
            sp[0]  = i;
            int jj = j0;
            while (jj) { int jn = sway[jj]; sp[jj] = sp[jn]; jj = jn; }
        }
        // deferred dual updates for used columns (telescoped sums):
        // v[j] -= deltaF - d[j]; su[old_row] = cinfo.x + (deltaF - d[j]).
        // Old rows are distinct (they formed a matching) => no write races.
        #pragma unroll
        for (int s = 0; s < 4; s++) {
            if ((usedm >> s) & 1u) {
                int jj = jbase + s;
                float dd = deltaF - d[s];
                v[s] -= dd;
                float2 cio = cinfo[jj];          // pre-augment {u, row}
                int rold = __float_as_int(cio.y);
                su[rold] = cio.x + dd;
            }
        }
        __syncwarp();

        // refresh cached {u,row} for used columns AND the break column j0
        #pragma unroll
        for (int s = 0; s < 4; s++) {
            int jj = jbase + s;
            if (((usedm >> s) & 1u) || (jj == j0)) {
                int r = sp[jj];
                cinfo[jj] = make_float2(su[r], __int_as_float(r));
            }
        }
        __syncwarp();
    }

    for (int j = lane + 1; j <= NN; j += 32)
        g_col[b * NN + (sp[j] - 1)] = j - 1;
}

// ---------------------------------------------------------------------------
// Kernel 3: per-batch losses.
// ---------------------------------------------------------------------------
__global__ void loss_kernel(const float* __restrict__ bbox_pred,
                            const float* __restrict__ labels_pred,
                            const float* __restrict__ bbox_gt,
                            const int*   __restrict__ labels_gt)
{
    int b   = blockIdx.x;
    int tid = threadIdx.x;  // 128

    double nll_sum = 0.0, reg_sum = 0.0, giou_sum = 0.0;

    for (int q2 = tid; q2 < NN; q2 += blockDim.x) {
        int cg  = g_col[b * NN + q2];
        int lab = labels_gt[b * NN + cg];

        const float* pr = labels_pred + (size_t)(b * NN + q2) * CC;
        double se = 0.0;
        float  plab = 0.0f;
        for (int c = 0; c < CC; c++) {
            float pc = fminf(fmaxf(pr[c], 1e-7f), 1.0f - 1e-7f);
            se += (double)pc;
            if (c == lab) plab = pc;
        }
        nll_sum += log(se) - (double)logf(plab);

        float4 p = ((const float4*)bbox_pred)[b * NN + q2];
        float4 t = ((const float4*)bbox_gt)[b * NN + cg];
        reg_sum += (double)(fabsf(p.x - t.x) + fabsf(p.y - t.y) +
                            fabsf(p.z - t.z) + fabsf(p.w - t.w));

        float4 g = ((const float4*)bbox_gt)[b * NN + q2];
        float pulx = p.x - 0.5f * p.z, puly = p.y - 0.5f * p.w;
        float pdrx = p.x + 0.5f * p.z, pdry = p.y + 0.5f * p.w;
        float gulx = g.x - 0.5f * g.z, guly = g.y - 0.5f * g.w;
        float gdrx = g.x + 0.5f * g.z, gdry = g.y + 0.5f * g.w;
        float iw = fmaxf(fminf(pdrx, gdrx) - fmaxf(pulx, gulx) + 1.0f, 0.0f);
        float ih = fmaxf(fminf(pdry, gdry) - fmaxf(puly, guly) + 1.0f, 0.0f);
        float inter = iw * ih;
        float pw = fmaxf(pdrx - pulx + 1.0f, 0.0f);
        float ph = fmaxf(pdry - puly + 1.0f, 0.0f);
        float gw = fmaxf(gdrx - gulx + 1.0f, 0.0f);
        float gh = fmaxf(gdry - guly + 1.0f, 0.0f);
        float uni = pw * ph + gw * gh - inter;
        float iou = inter / fmaxf(uni, 1e-9f);
        float bw = fmaxf(fmaxf(pdrx, gdrx) - fminf(pulx, gulx) + 1.0f, 0.0f);
        float bh = fmaxf(fmaxf(pdry, gdry) - fminf(puly, guly) + 1.0f, 0.0f);
        float bound = bw * bh;
        float bgr = (bound - uni) / fmaxf(bound, 1e-9f);
        giou_sum += (double)(iou - bgr);
    }

    __shared__ double s0[128], s1[128], s2[128];
    s0[tid] = nll_sum; s1[tid] = reg_sum; s2[tid] = giou_sum;
    __syncthreads();
    for (int s = 64; s; s >>= 1) {
        if (tid < s) { s0[tid] += s0[tid + s]; s1[tid] += s1[tid + s]; s2[tid] += s2[tid + s]; }
        __syncthreads();
    }
    if (tid == 0) {
        double per = s0[0] / NN + 5.0 * (s1[0] / (NN * 4.0)) + 2.0 * (s2[0] / NN);
        g_partial[b] = per;
    }
}

__global__ void final_kernel(float* __restrict__ out)
{
    double s = 0.0;
    for (int b = 0; b < BB; b++) s += g_partial[b];
    out[0] = (float)s;
}

// ---------------------------------------------------------------------------
extern "C" void kernel_launch(void* const* d_in, const int* in_sizes, int n_in,
                              void* d_out, int out_size)
{
    const float* bbox_pred   = (const float*)d_in[0];
    const float* labels_pred = (const float*)d_in[1];
    const float* bbox_gt     = (const float*)d_in[2];
    const int*   labels_gt   = (const int*)d_in[3];

    cost_kernel<<<BB, 256>>>(bbox_pred, labels_pred, bbox_gt, labels_gt);
    hungarian_kernel<<<BB, 32>>>();
    loss_kernel<<<BB, 128>>>(bbox_pred, labels_pred, bbox_gt, labels_gt);
    final_kernel<<<1, 1>>>((float*)d_out);
}